// round 14
// baseline (speedup 1.0000x reference)
#include <cuda_runtime.h>
#include <cuda_fp16.h>
#include <math.h>
#include <stdint.h>

#define THREADS 256
#define TB      128          // rows per CTA (8 warps x 16 rows)
#define NCH     48           // 768 / 16
#define HD      96

// ---- precomputed weight data (device globals; allocation-free scratch) ----
// fragment-order fp16: [ch][j][lane][reg][half] -> u16
__device__ unsigned short g_Bhi16[NCH * 12 * 32 * 2 * 2];
__device__ unsigned short g_Blo16[NCH * 12 * 32 * 2 * 2];
__device__ float g_C1[HD];        // sum_d beta*w1 + b1
__device__ float g_C2[HD];        // sum_d gamma*w1 (all 771 d)
__device__ float g_WT[3 * HD];    // gamma[768+j]*w1[768+j][n]

// ======================= setup kernels =======================

__global__ void fh_prep_b(const float* __restrict__ gamma,
                          const float* __restrict__ w1) {
    const int idx = blockIdx.x * 256 + threadIdx.x;
    if (idx >= 768 * HD) return;
    const int k = idx / HD, n = idx % HD;
    const float wt = __ldg(&gamma[k]) * __ldg(&w1[(size_t)k * HD + n]);
    const __half hb = __float2half_rn(wt);
    const float hf = __half2float(hb);
    const __half lb = __float2half_rn(wt - hf);
    const int ch = k >> 4, kk = k & 15;
    const int j = n >> 3, gg = n & 7;
    const int t = (kk & 7) >> 1, half = kk & 1, reg = kk >> 3;
    const int l = gg * 4 + t;
    const int off = ((((ch * 12 + j) * 32 + l) * 2 + reg) * 2 + half);
    g_Bhi16[off] = *(const unsigned short*)&hb;
    g_Blo16[off] = *(const unsigned short*)&lb;
}

__global__ void fh_prep_c(const float* __restrict__ gamma,
                          const float* __restrict__ beta,
                          const float* __restrict__ w1,
                          const float* __restrict__ b1) {
    const int n = blockIdx.x;            // 96 blocks
    const int tid = threadIdx.x;         // 256 threads
    float c1 = 0.f, c2 = 0.f;
    for (int k = tid; k < 768; k += 256) {
        const float w = __ldg(&w1[(size_t)k * HD + n]);
        c2 = fmaf(__ldg(&gamma[k]), w, c2);
        c1 = fmaf(__ldg(&beta[k]),  w, c1);
    }
    #pragma unroll
    for (int m = 16; m > 0; m >>= 1) {
        c1 += __shfl_xor_sync(0xffffffffu, c1, m);
        c2 += __shfl_xor_sync(0xffffffffu, c2, m);
    }
    __shared__ float s1[8], s2[8];
    if ((tid & 31) == 0) { s1[tid >> 5] = c1; s2[tid >> 5] = c2; }
    __syncthreads();
    if (tid == 0) {
        c1 = 0.f; c2 = 0.f;
        #pragma unroll
        for (int i = 0; i < 8; ++i) { c1 += s1[i]; c2 += s2[i]; }
        c1 += __ldg(&b1[n]);
        #pragma unroll
        for (int j = 0; j < 3; ++j) {
            const float w  = __ldg(&w1[(size_t)(768 + j) * HD + n]);
            const float wt = __ldg(&gamma[768 + j]) * w;
            g_WT[j * HD + n] = wt;
            c2 += wt;
            c1 = fmaf(__ldg(&beta[768 + j]), w, c1);
        }
        g_C1[n] = c1;
        g_C2[n] = c2;
    }
}

// ======================= main kernel =======================

// pack two f32 -> f16x2, first operand in the HIGH half
__device__ __forceinline__ uint32_t pack_f16x2(float hi, float lo) {
    uint32_t r;
    asm("cvt.rn.f16x2.f32 %0, %1, %2;" : "=r"(r) : "f"(hi), "f"(lo));
    return r;
}

__device__ __forceinline__ void mma16816(float* c, const uint32_t* a, uint2 b) {
    asm volatile(
        "mma.sync.aligned.m16n8k16.row.col.f32.f16.f16.f32 "
        "{%0,%1,%2,%3}, {%4,%5,%6,%7}, {%8,%9}, {%0,%1,%2,%3};\n"
        : "+f"(c[0]), "+f"(c[1]), "+f"(c[2]), "+f"(c[3])
        : "r"(a[0]), "r"(a[1]), "r"(a[2]), "r"(a[3]), "r"(b.x), "r"(b.y));
}

__device__ __forceinline__ void cpa16(uint32_t d, const void* s) {
    asm volatile("cp.async.cg.shared.global [%0], [%1], 16;" :: "r"(d), "l"(s) : "memory");
}

__device__ __forceinline__ uint32_t smem_u32(const void* p) {
    return (uint32_t)__cvta_generic_to_shared(p);
}

__global__ __launch_bounds__(THREADS)
void fh_main(const float* __restrict__ emb,
             const float* __restrict__ tree,
             const float* __restrict__ w2,
             const float* __restrict__ b2,
             float* __restrict__ out)
{
    __shared__ __align__(16) unsigned char sB[2][6144];   // per buf: [hi 3072][lo 3072]
    __shared__ float sC1[HD], sC2[HD], sWT[3 * HD], sW2[HD * 3];
    __shared__ float sMU[TB], sRS[TB], sT[TB * 3];

    const int tid = threadIdx.x;
    const int w   = tid >> 5;
    const int l   = tid & 31;
    const int g   = l >> 2;
    const int t   = l & 3;
    const size_t rowbase = (size_t)blockIdx.x * TB;
    const int wrow = w * 16;

    // tables
    if (tid < HD) { sC1[tid] = g_C1[tid]; sC2[tid] = g_C2[tid]; }
    for (int i = tid; i < 3 * HD; i += THREADS) {
        sWT[i] = g_WT[i];
        sW2[i] = __ldg(&w2[i]);
    }

    // prefetch B chunk 0
    if (tid < 192) {
        cpa16(smem_u32(&sB[0][tid * 16]),        (const char*)g_Bhi16 + tid * 16);
        cpa16(smem_u32(&sB[0][3072 + tid * 16]), (const char*)g_Blo16 + tid * 16);
    }
    asm volatile("cp.async.commit_group;" ::: "memory");

    float acc[12][4];
    #pragma unroll
    for (int j = 0; j < 12; ++j)
        #pragma unroll
        for (int c = 0; c < 4; ++c) acc[j][c] = 0.f;

    float s2r[2] = {0.f, 0.f};
    float q2r[2] = {0.f, 0.f};

    // row pointers for h: row = wrow + 8*h + g, col offset 2t
    const float* rp[2];
    #pragma unroll
    for (int h = 0; h < 2; ++h)
        rp[h] = emb + (rowbase + wrow + 8 * h + g) * 768 + 2 * t;

    // raw A double buffer (registers), preload chunk 0
    float2 raw[2][2][2];     // [buf][h][v0/v1]
    #pragma unroll
    for (int h = 0; h < 2; ++h) {
        raw[0][h][0] = __ldg((const float2*)(rp[h]));
        raw[0][h][1] = __ldg((const float2*)(rp[h] + 8));
    }

    #pragma unroll 2
    for (int ch = 0; ch < NCH; ++ch) {
        const int pb = ch & 1;

        // ---- convert raw A -> fp16 fragments + stats ----
        uint32_t ah[4];
        #pragma unroll
        for (int h = 0; h < 2; ++h) {
            const float2 v0 = raw[pb][h][0];
            const float2 v1 = raw[pb][h][1];
            ah[h]     = pack_f16x2(v0.y, v0.x);
            ah[h + 2] = pack_f16x2(v1.y, v1.x);
            s2r[h] += (v0.x + v0.y) + (v1.x + v1.y);
            q2r[h] = fmaf(v0.x, v0.x, q2r[h]);
            q2r[h] = fmaf(v0.y, v0.y, q2r[h]);
            q2r[h] = fmaf(v1.x, v1.x, q2r[h]);
            q2r[h] = fmaf(v1.y, v1.y, q2r[h]);
        }

        // ---- prefetch A raw for ch+1 (latency hidden behind MMA phase) ----
        if (ch + 1 < NCH) {
            const float* base0 = rp[0] + (ch + 1) * 16;
            const float* base1 = rp[1] + (ch + 1) * 16;
            raw[pb ^ 1][0][0] = __ldg((const float2*)(base0));
            raw[pb ^ 1][0][1] = __ldg((const float2*)(base0 + 8));
            raw[pb ^ 1][1][0] = __ldg((const float2*)(base1));
            raw[pb ^ 1][1][1] = __ldg((const float2*)(base1 + 8));
        }

        // ---- prefetch next B chunk, wait for current ----
        if (ch + 1 < NCH) {
            if (tid < 192) {
                const int buf = (ch + 1) & 1;
                cpa16(smem_u32(&sB[buf][tid * 16]),
                      (const char*)g_Bhi16 + (ch + 1) * 3072 + tid * 16);
                cpa16(smem_u32(&sB[buf][3072 + tid * 16]),
                      (const char*)g_Blo16 + (ch + 1) * 3072 + tid * 16);
            }
            asm volatile("cp.async.commit_group;" ::: "memory");
            asm volatile("cp.async.wait_group 1;" ::: "memory");
        } else {
            asm volatile("cp.async.wait_group 0;" ::: "memory");
        }
        __syncthreads();

        // ---- MMAs: 2 passes (B hi, B lo); same-acc deps 12 MMAs apart ----
        const unsigned char* base = sB[pb];
        #pragma unroll
        for (int j = 0; j < 12; ++j) {
            const uint2 bh = *(const uint2*)(base + j * 256 + l * 8);
            mma16816(acc[j], ah, bh);
        }
        #pragma unroll
        for (int j = 0; j < 12; ++j) {
            const uint2 bl = *(const uint2*)(base + 3072 + j * 256 + l * 8);
            mma16816(acc[j], ah, bl);
        }
        __syncthreads();   // everyone done reading before this buf is refilled
    }

    // ---- row stats: reduce over the 4 quad lanes, add tree tail ----
    #pragma unroll
    for (int m = 1; m <= 2; m <<= 1) {
        #pragma unroll
        for (int h = 0; h < 2; ++h) {
            s2r[h] += __shfl_xor_sync(0xffffffffu, s2r[h], m);
            q2r[h] += __shfl_xor_sync(0xffffffffu, q2r[h], m);
        }
    }
    if (t == 0) {
        #pragma unroll
        for (int h = 0; h < 2; ++h) {
            const int lr = wrow + 8 * h + g;
            const size_t gr = rowbase + lr;
            const float t0 = __ldg(&tree[gr * 3 + 0]);
            const float t1 = __ldg(&tree[gr * 3 + 1]);
            const float t2 = __ldg(&tree[gr * 3 + 2]);
            const float s = s2r[h] + t0 + t1 + t2;
            const float q = q2r[h] + t0 * t0 + t1 * t1 + t2 * t2;
            const float mu = s * (1.0f / 771.0f);
            const float rs = rsqrtf(q * (1.0f / 771.0f) - mu * mu + 1e-5f);
            sMU[lr] = mu; sRS[lr] = rs;
            sT[lr * 3 + 0] = t0; sT[lr * 3 + 1] = t1; sT[lr * 3 + 2] = t2;
        }
    }
    __syncthreads();

    // ---- epilogue: LN-fold + bias + exact GELU + GEMM2 partials ----
    float mu[2], rs[2], tv[2][3];
    #pragma unroll
    for (int h = 0; h < 2; ++h) {
        const int lr = wrow + 8 * h + g;
        mu[h] = sMU[lr]; rs[h] = sRS[lr];
        tv[h][0] = sT[lr * 3 + 0];
        tv[h][1] = sT[lr * 3 + 1];
        tv[h][2] = sT[lr * 3 + 2];
    }
    float o[2][3];
    #pragma unroll
    for (int h = 0; h < 2; ++h)
        #pragma unroll
        for (int c = 0; c < 3; ++c) o[h][c] = 0.f;

    #pragma unroll
    for (int j = 0; j < 12; ++j) {
        const int n0 = 8 * j + 2 * t;
        float c2v[2] = {sC2[n0], sC2[n0 + 1]};
        float c1v[2] = {sC1[n0], sC1[n0 + 1]};
        float wt0[2] = {sWT[n0], sWT[n0 + 1]};
        float wt1[2] = {sWT[HD + n0], sWT[HD + n0 + 1]};
        float wt2[2] = {sWT[2 * HD + n0], sWT[2 * HD + n0 + 1]};
        float w2v[2][3];
        #pragma unroll
        for (int cc = 0; cc < 2; ++cc)
            #pragma unroll
            for (int c = 0; c < 3; ++c)
                w2v[cc][c] = sW2[(n0 + cc) * 3 + c];

        #pragma unroll
        for (int h = 0; h < 2; ++h) {
            #pragma unroll
            for (int cc = 0; cc < 2; ++cc) {
                const float a = acc[j][2 * h + cc];
                const float tail = tv[h][0] * wt0[cc] +
                                   tv[h][1] * wt1[cc] +
                                   tv[h][2] * wt2[cc];
                const float y = rs[h] * (a + tail - mu[h] * c2v[cc]) + c1v[cc];
                const float gl = 0.5f * y * (1.0f + erff(y * 0.70710678118654752f));
                o[h][0] = fmaf(gl, w2v[cc][0], o[h][0]);
                o[h][1] = fmaf(gl, w2v[cc][1], o[h][1]);
                o[h][2] = fmaf(gl, w2v[cc][2], o[h][2]);
            }
        }
    }

    #pragma unroll
    for (int m = 1; m <= 2; m <<= 1)
        #pragma unroll
        for (int h = 0; h < 2; ++h)
            #pragma unroll
            for (int c = 0; c < 3; ++c)
                o[h][c] += __shfl_xor_sync(0xffffffffu, o[h][c], m);

    if (t == 0) {
        const float b20 = __ldg(&b2[0]);
        const float b21 = __ldg(&b2[1]);
        const float b22 = __ldg(&b2[2]);
        #pragma unroll
        for (int h = 0; h < 2; ++h) {
            const size_t gr = rowbase + wrow + 8 * h + g;
            out[gr * 3 + 0] = o[h][0] + b20;
            out[gr * 3 + 1] = o[h][1] + b21;
            out[gr * 3 + 2] = o[h][2] + b22;
        }
    }
}

extern "C" void kernel_launch(void* const* d_in, const int* in_sizes, int n_in,
                              void* d_out, int out_size) {
    const float* emb   = (const float*)d_in[0];
    const float* tree  = (const float*)d_in[1];
    const float* gamma = (const float*)d_in[2];
    const float* beta  = (const float*)d_in[3];
    const float* w1    = (const float*)d_in[4];
    const float* b1    = (const float*)d_in[5];
    const float* w2    = (const float*)d_in[6];
    const float* b2    = (const float*)d_in[7];
    float* out = (float*)d_out;

    const int B = in_sizes[0] / 768;

    fh_prep_b<<<(768 * HD + 255) / 256, 256>>>(gamma, w1);
    fh_prep_c<<<HD, 256>>>(gamma, beta, w1, b1);
    fh_main<<<B / TB, THREADS>>>(emb, tree, w2, b2, out);
}

// round 15
// speedup vs baseline: 1.0075x; 1.0075x over previous
#include <cuda_runtime.h>
#include <cuda_fp16.h>
#include <math.h>
#include <stdint.h>

#define THREADS 256
#define TB      128          // rows per CTA (8 warps x 16 rows)
#define NCH     48           // 768 / 16
#define HD      96

// ---- precomputed weight data (device globals; allocation-free scratch) ----
// fragment-order fp16: [ch][j][lane][reg][half] -> u16
__device__ unsigned short g_Bhi16[NCH * 12 * 32 * 2 * 2];
__device__ unsigned short g_Blo16[NCH * 12 * 32 * 2 * 2];
__device__ float g_C1[HD];        // sum_d beta*w1 + b1
__device__ float g_C2[HD];        // sum_d gamma*w1 (all 771 d)
__device__ float g_WT[3 * HD];    // gamma[768+j]*w1[768+j][n]

// ======================= setup kernels =======================

__global__ void fh_prep_b(const float* __restrict__ gamma,
                          const float* __restrict__ w1) {
    const int idx = blockIdx.x * 256 + threadIdx.x;
    if (idx >= 768 * HD) return;
    const int k = idx / HD, n = idx % HD;
    const float wt = __ldg(&gamma[k]) * __ldg(&w1[(size_t)k * HD + n]);
    const __half hb = __float2half_rn(wt);
    const float hf = __half2float(hb);
    const __half lb = __float2half_rn(wt - hf);
    const int ch = k >> 4, kk = k & 15;
    const int j = n >> 3, gg = n & 7;
    const int t = (kk & 7) >> 1, half = kk & 1, reg = kk >> 3;
    const int l = gg * 4 + t;
    const int off = ((((ch * 12 + j) * 32 + l) * 2 + reg) * 2 + half);
    g_Bhi16[off] = *(const unsigned short*)&hb;
    g_Blo16[off] = *(const unsigned short*)&lb;
}

__global__ void fh_prep_c(const float* __restrict__ gamma,
                          const float* __restrict__ beta,
                          const float* __restrict__ w1,
                          const float* __restrict__ b1) {
    const int n = blockIdx.x;            // 96 blocks
    const int tid = threadIdx.x;         // 256 threads
    float c1 = 0.f, c2 = 0.f;
    for (int k = tid; k < 768; k += 256) {
        const float w = __ldg(&w1[(size_t)k * HD + n]);
        c2 = fmaf(__ldg(&gamma[k]), w, c2);
        c1 = fmaf(__ldg(&beta[k]),  w, c1);
    }
    #pragma unroll
    for (int m = 16; m > 0; m >>= 1) {
        c1 += __shfl_xor_sync(0xffffffffu, c1, m);
        c2 += __shfl_xor_sync(0xffffffffu, c2, m);
    }
    __shared__ float s1[8], s2[8];
    if ((tid & 31) == 0) { s1[tid >> 5] = c1; s2[tid >> 5] = c2; }
    __syncthreads();
    if (tid == 0) {
        c1 = 0.f; c2 = 0.f;
        #pragma unroll
        for (int i = 0; i < 8; ++i) { c1 += s1[i]; c2 += s2[i]; }
        c1 += __ldg(&b1[n]);
        #pragma unroll
        for (int j = 0; j < 3; ++j) {
            const float w  = __ldg(&w1[(size_t)(768 + j) * HD + n]);
            const float wt = __ldg(&gamma[768 + j]) * w;
            g_WT[j * HD + n] = wt;
            c2 += wt;
            c1 = fmaf(__ldg(&beta[768 + j]), w, c1);
        }
        g_C1[n] = c1;
        g_C2[n] = c2;
    }
}

// ======================= main kernel =======================

// pack two f32 -> f16x2, first operand in the HIGH half
__device__ __forceinline__ uint32_t pack_f16x2(float hi, float lo) {
    uint32_t r;
    asm("cvt.rn.f16x2.f32 %0, %1, %2;" : "=r"(r) : "f"(hi), "f"(lo));
    return r;
}

__device__ __forceinline__ void mma16816(float* c, const uint32_t* a, uint2 b) {
    asm volatile(
        "mma.sync.aligned.m16n8k16.row.col.f32.f16.f16.f32 "
        "{%0,%1,%2,%3}, {%4,%5,%6,%7}, {%8,%9}, {%0,%1,%2,%3};\n"
        : "+f"(c[0]), "+f"(c[1]), "+f"(c[2]), "+f"(c[3])
        : "r"(a[0]), "r"(a[1]), "r"(a[2]), "r"(a[3]), "r"(b.x), "r"(b.y));
}

__device__ __forceinline__ void cpa16(uint32_t d, const void* s) {
    asm volatile("cp.async.cg.shared.global [%0], [%1], 16;" :: "r"(d), "l"(s) : "memory");
}

__device__ __forceinline__ uint32_t smem_u32(const void* p) {
    return (uint32_t)__cvta_generic_to_shared(p);
}

__global__ __launch_bounds__(THREADS)
void fh_main(const float* __restrict__ emb,
             const float* __restrict__ tree,
             const float* __restrict__ w2,
             const float* __restrict__ b2,
             float* __restrict__ out)
{
    __shared__ __align__(16) unsigned char sB[2][6144];   // per buf: [hi 3072][lo 3072]
    __shared__ float sC1[HD], sC2[HD], sWT[3 * HD], sW2[HD * 3];
    __shared__ float sMU[TB], sRS[TB], sT[TB * 3];

    const int tid = threadIdx.x;
    const int w   = tid >> 5;
    const int l   = tid & 31;
    const int g   = l >> 2;
    const int t   = l & 3;
    const size_t rowbase = (size_t)blockIdx.x * TB;
    const int wrow = w * 16;

    // tables
    if (tid < HD) { sC1[tid] = g_C1[tid]; sC2[tid] = g_C2[tid]; }
    for (int i = tid; i < 3 * HD; i += THREADS) {
        sWT[i] = g_WT[i];
        sW2[i] = __ldg(&w2[i]);
    }

    // prefetch B chunk 0
    if (tid < 192) {
        cpa16(smem_u32(&sB[0][tid * 16]),        (const char*)g_Bhi16 + tid * 16);
        cpa16(smem_u32(&sB[0][3072 + tid * 16]), (const char*)g_Blo16 + tid * 16);
    }
    asm volatile("cp.async.commit_group;" ::: "memory");

    float acc[12][4];
    #pragma unroll
    for (int j = 0; j < 12; ++j)
        #pragma unroll
        for (int c = 0; c < 4; ++c) acc[j][c] = 0.f;

    float s2r[2] = {0.f, 0.f};
    float q2r[2] = {0.f, 0.f};

    // row pointers for h: row = wrow + 8*h + g, col offset 2t
    const float* rp[2];
    #pragma unroll
    for (int h = 0; h < 2; ++h)
        rp[h] = emb + (rowbase + wrow + 8 * h + g) * 768 + 2 * t;

    // raw A double buffer (registers), preload chunk 0
    float2 raw[2][2][2];     // [buf][h][v0/v1]
    #pragma unroll
    for (int h = 0; h < 2; ++h) {
        raw[0][h][0] = __ldg((const float2*)(rp[h]));
        raw[0][h][1] = __ldg((const float2*)(rp[h] + 8));
    }

    #pragma unroll 2
    for (int ch = 0; ch < NCH; ++ch) {
        const int pb = ch & 1;

        // ---- convert raw A -> fp16 fragments + stats ----
        uint32_t ah[4];
        #pragma unroll
        for (int h = 0; h < 2; ++h) {
            const float2 v0 = raw[pb][h][0];
            const float2 v1 = raw[pb][h][1];
            ah[h]     = pack_f16x2(v0.y, v0.x);
            ah[h + 2] = pack_f16x2(v1.y, v1.x);
            s2r[h] += (v0.x + v0.y) + (v1.x + v1.y);
            q2r[h] = fmaf(v0.x, v0.x, q2r[h]);
            q2r[h] = fmaf(v0.y, v0.y, q2r[h]);
            q2r[h] = fmaf(v1.x, v1.x, q2r[h]);
            q2r[h] = fmaf(v1.y, v1.y, q2r[h]);
        }

        // ---- prefetch A raw for ch+1 (latency hidden behind MMA phase) ----
        if (ch + 1 < NCH) {
            const float* base0 = rp[0] + (ch + 1) * 16;
            const float* base1 = rp[1] + (ch + 1) * 16;
            raw[pb ^ 1][0][0] = __ldg((const float2*)(base0));
            raw[pb ^ 1][0][1] = __ldg((const float2*)(base0 + 8));
            raw[pb ^ 1][1][0] = __ldg((const float2*)(base1));
            raw[pb ^ 1][1][1] = __ldg((const float2*)(base1 + 8));
        }

        // ---- prefetch next B chunk, wait for current ----
        if (ch + 1 < NCH) {
            if (tid < 192) {
                const int buf = (ch + 1) & 1;
                cpa16(smem_u32(&sB[buf][tid * 16]),
                      (const char*)g_Bhi16 + (ch + 1) * 3072 + tid * 16);
                cpa16(smem_u32(&sB[buf][3072 + tid * 16]),
                      (const char*)g_Blo16 + (ch + 1) * 3072 + tid * 16);
            }
            asm volatile("cp.async.commit_group;" ::: "memory");
            asm volatile("cp.async.wait_group 1;" ::: "memory");
        } else {
            asm volatile("cp.async.wait_group 0;" ::: "memory");
        }
        __syncthreads();

        // ---- MMAs: 2 passes (B hi, B lo); same-acc deps 12 MMAs apart ----
        const unsigned char* base = sB[pb];
        #pragma unroll
        for (int j = 0; j < 12; ++j) {
            const uint2 bh = *(const uint2*)(base + j * 256 + l * 8);
            mma16816(acc[j], ah, bh);
        }
        #pragma unroll
        for (int j = 0; j < 12; ++j) {
            const uint2 bl = *(const uint2*)(base + 3072 + j * 256 + l * 8);
            mma16816(acc[j], ah, bl);
        }
        __syncthreads();   // everyone done reading before this buf is refilled
    }

    // ---- row stats: reduce over the 4 quad lanes, add tree tail ----
    #pragma unroll
    for (int m = 1; m <= 2; m <<= 1) {
        #pragma unroll
        for (int h = 0; h < 2; ++h) {
            s2r[h] += __shfl_xor_sync(0xffffffffu, s2r[h], m);
            q2r[h] += __shfl_xor_sync(0xffffffffu, q2r[h], m);
        }
    }
    if (t == 0) {
        #pragma unroll
        for (int h = 0; h < 2; ++h) {
            const int lr = wrow + 8 * h + g;
            const size_t gr = rowbase + lr;
            const float t0 = __ldg(&tree[gr * 3 + 0]);
            const float t1 = __ldg(&tree[gr * 3 + 1]);
            const float t2 = __ldg(&tree[gr * 3 + 2]);
            const float s = s2r[h] + t0 + t1 + t2;
            const float q = q2r[h] + t0 * t0 + t1 * t1 + t2 * t2;
            const float mu = s * (1.0f / 771.0f);
            const float rs = rsqrtf(q * (1.0f / 771.0f) - mu * mu + 1e-5f);
            sMU[lr] = mu; sRS[lr] = rs;
            sT[lr * 3 + 0] = t0; sT[lr * 3 + 1] = t1; sT[lr * 3 + 2] = t2;
        }
    }
    __syncthreads();

    // ---- epilogue: LN-fold + bias + exact GELU + GEMM2 partials ----
    float mu[2], rs[2], tv[2][3];
    #pragma unroll
    for (int h = 0; h < 2; ++h) {
        const int lr = wrow + 8 * h + g;
        mu[h] = sMU[lr]; rs[h] = sRS[lr];
        tv[h][0] = sT[lr * 3 + 0];
        tv[h][1] = sT[lr * 3 + 1];
        tv[h][2] = sT[lr * 3 + 2];
    }
    float o[2][3];
    #pragma unroll
    for (int h = 0; h < 2; ++h)
        #pragma unroll
        for (int c = 0; c < 3; ++c) o[h][c] = 0.f;

    #pragma unroll
    for (int j = 0; j < 12; ++j) {
        const int n0 = 8 * j + 2 * t;
        float c2v[2] = {sC2[n0], sC2[n0 + 1]};
        float c1v[2] = {sC1[n0], sC1[n0 + 1]};
        float wt0[2] = {sWT[n0], sWT[n0 + 1]};
        float wt1[2] = {sWT[HD + n0], sWT[HD + n0 + 1]};
        float wt2[2] = {sWT[2 * HD + n0], sWT[2 * HD + n0 + 1]};
        float w2v[2][3];
        #pragma unroll
        for (int cc = 0; cc < 2; ++cc)
            #pragma unroll
            for (int c = 0; c < 3; ++c)
                w2v[cc][c] = sW2[(n0 + cc) * 3 + c];

        #pragma unroll
        for (int h = 0; h < 2; ++h) {
            #pragma unroll
            for (int cc = 0; cc < 2; ++cc) {
                const float a = acc[j][2 * h + cc];
                const float tail = tv[h][0] * wt0[cc] +
                                   tv[h][1] * wt1[cc] +
                                   tv[h][2] * wt2[cc];
                const float y = rs[h] * (a + tail - mu[h] * c2v[cc]) + c1v[cc];
                const float gl = 0.5f * y * (1.0f + erff(y * 0.70710678118654752f));
                o[h][0] = fmaf(gl, w2v[cc][0], o[h][0]);
                o[h][1] = fmaf(gl, w2v[cc][1], o[h][1]);
                o[h][2] = fmaf(gl, w2v[cc][2], o[h][2]);
            }
        }
    }

    #pragma unroll
    for (int m = 1; m <= 2; m <<= 1)
        #pragma unroll
        for (int h = 0; h < 2; ++h)
            #pragma unroll
            for (int c = 0; c < 3; ++c)
                o[h][c] += __shfl_xor_sync(0xffffffffu, o[h][c], m);

    if (t == 0) {
        const float b20 = __ldg(&b2[0]);
        const float b21 = __ldg(&b2[1]);
        const float b22 = __ldg(&b2[2]);
        #pragma unroll
        for (int h = 0; h < 2; ++h) {
            const size_t gr = rowbase + wrow + 8 * h + g;
            out[gr * 3 + 0] = o[h][0] + b20;
            out[gr * 3 + 1] = o[h][1] + b21;
            out[gr * 3 + 2] = o[h][2] + b22;
        }
    }
}

extern "C" void kernel_launch(void* const* d_in, const int* in_sizes, int n_in,
                              void* d_out, int out_size) {
    const float* emb   = (const float*)d_in[0];
    const float* tree  = (const float*)d_in[1];
    const float* gamma = (const float*)d_in[2];
    const float* beta  = (const float*)d_in[3];
    const float* w1    = (const float*)d_in[4];
    const float* b1    = (const float*)d_in[5];
    const float* w2    = (const float*)d_in[6];
    const float* b2    = (const float*)d_in[7];
    float* out = (float*)d_out;

    const int B = in_sizes[0] / 768;

    fh_prep_b<<<(768 * HD + 255) / 256, 256>>>(gamma, w1);
    fh_prep_c<<<HD, 256>>>(gamma, beta, w1, b1);
    fh_main<<<B / TB, THREADS>>>(emb, tree, w2, b2, out);
}

// round 16
// speedup vs baseline: 1.0076x; 1.0002x over previous
#include <cuda_runtime.h>
#include <cuda_fp16.h>
#include <math.h>
#include <stdint.h>

#define THREADS 256
#define TB      128          // rows per CTA (8 warps x 16 rows)
#define NCH     48           // 768 / 16
#define HD      96

// ---- precomputed weight data (device globals; allocation-free scratch) ----
// fragment-order fp16: [ch][j][lane][reg][half] -> u16
__device__ unsigned short g_Bhi16[NCH * 12 * 32 * 2 * 2];
__device__ unsigned short g_Blo16[NCH * 12 * 32 * 2 * 2];
__device__ float g_C1[HD];        // sum_d beta*w1 + b1
__device__ float g_C2[HD];        // sum_d gamma*w1 (all 771 d)
__device__ float g_WT[3 * HD];    // gamma[768+j]*w1[768+j][n]

// ======================= setup kernels =======================

__global__ void fh_prep_b(const float* __restrict__ gamma,
                          const float* __restrict__ w1) {
    const int idx = blockIdx.x * 256 + threadIdx.x;
    if (idx >= 768 * HD) return;
    const int k = idx / HD, n = idx % HD;
    const float wt = __ldg(&gamma[k]) * __ldg(&w1[(size_t)k * HD + n]);
    const __half hb = __float2half_rn(wt);
    const float hf = __half2float(hb);
    const __half lb = __float2half_rn(wt - hf);
    const int ch = k >> 4, kk = k & 15;
    const int j = n >> 3, gg = n & 7;
    const int t = (kk & 7) >> 1, half = kk & 1, reg = kk >> 3;
    const int l = gg * 4 + t;
    const int off = ((((ch * 12 + j) * 32 + l) * 2 + reg) * 2 + half);
    g_Bhi16[off] = *(const unsigned short*)&hb;
    g_Blo16[off] = *(const unsigned short*)&lb;
}

__global__ void fh_prep_c(const float* __restrict__ gamma,
                          const float* __restrict__ beta,
                          const float* __restrict__ w1,
                          const float* __restrict__ b1) {
    const int n = blockIdx.x;            // 96 blocks
    const int tid = threadIdx.x;         // 256 threads
    float c1 = 0.f, c2 = 0.f;
    for (int k = tid; k < 768; k += 256) {
        const float w = __ldg(&w1[(size_t)k * HD + n]);
        c2 = fmaf(__ldg(&gamma[k]), w, c2);
        c1 = fmaf(__ldg(&beta[k]),  w, c1);
    }
    #pragma unroll
    for (int m = 16; m > 0; m >>= 1) {
        c1 += __shfl_xor_sync(0xffffffffu, c1, m);
        c2 += __shfl_xor_sync(0xffffffffu, c2, m);
    }
    __shared__ float s1[8], s2[8];
    if ((tid & 31) == 0) { s1[tid >> 5] = c1; s2[tid >> 5] = c2; }
    __syncthreads();
    if (tid == 0) {
        c1 = 0.f; c2 = 0.f;
        #pragma unroll
        for (int i = 0; i < 8; ++i) { c1 += s1[i]; c2 += s2[i]; }
        c1 += __ldg(&b1[n]);
        #pragma unroll
        for (int j = 0; j < 3; ++j) {
            const float w  = __ldg(&w1[(size_t)(768 + j) * HD + n]);
            const float wt = __ldg(&gamma[768 + j]) * w;
            g_WT[j * HD + n] = wt;
            c2 += wt;
            c1 = fmaf(__ldg(&beta[768 + j]), w, c1);
        }
        g_C1[n] = c1;
        g_C2[n] = c2;
    }
}

// ======================= main kernel =======================

// pack two f32 -> f16x2, first operand in the HIGH half
__device__ __forceinline__ uint32_t pack_f16x2(float hi, float lo) {
    uint32_t r;
    asm("cvt.rn.f16x2.f32 %0, %1, %2;" : "=r"(r) : "f"(hi), "f"(lo));
    return r;
}

__device__ __forceinline__ void mma16816(float* c, const uint32_t* a, uint2 b) {
    asm volatile(
        "mma.sync.aligned.m16n8k16.row.col.f32.f16.f16.f32 "
        "{%0,%1,%2,%3}, {%4,%5,%6,%7}, {%8,%9}, {%0,%1,%2,%3};\n"
        : "+f"(c[0]), "+f"(c[1]), "+f"(c[2]), "+f"(c[3])
        : "r"(a[0]), "r"(a[1]), "r"(a[2]), "r"(a[3]), "r"(b.x), "r"(b.y));
}

__device__ __forceinline__ void cpa16(uint32_t d, const void* s) {
    asm volatile("cp.async.cg.shared.global [%0], [%1], 16;" :: "r"(d), "l"(s) : "memory");
}

__device__ __forceinline__ uint32_t smem_u32(const void* p) {
    return (uint32_t)__cvta_generic_to_shared(p);
}

__global__ __launch_bounds__(THREADS)
void fh_main(const float* __restrict__ emb,
             const float* __restrict__ tree,
             const float* __restrict__ w2,
             const float* __restrict__ b2,
             float* __restrict__ out)
{
    __shared__ __align__(16) unsigned char sB[2][6144];   // per buf: [hi 3072][lo 3072]
    __shared__ float sC1[HD], sC2[HD], sWT[3 * HD], sW2[HD * 3];
    __shared__ float sMU[TB], sRS[TB], sT[TB * 3];

    const int tid = threadIdx.x;
    const int w   = tid >> 5;
    const int l   = tid & 31;
    const int g   = l >> 2;
    const int t   = l & 3;
    const size_t rowbase = (size_t)blockIdx.x * TB;
    const int wrow = w * 16;

    // tables
    if (tid < HD) { sC1[tid] = g_C1[tid]; sC2[tid] = g_C2[tid]; }
    for (int i = tid; i < 3 * HD; i += THREADS) {
        sWT[i] = g_WT[i];
        sW2[i] = __ldg(&w2[i]);
    }

    // prefetch B chunk 0
    if (tid < 192) {
        cpa16(smem_u32(&sB[0][tid * 16]),        (const char*)g_Bhi16 + tid * 16);
        cpa16(smem_u32(&sB[0][3072 + tid * 16]), (const char*)g_Blo16 + tid * 16);
    }
    asm volatile("cp.async.commit_group;" ::: "memory");

    float acc[12][4];
    #pragma unroll
    for (int j = 0; j < 12; ++j)
        #pragma unroll
        for (int c = 0; c < 4; ++c) acc[j][c] = 0.f;

    float s2r[2] = {0.f, 0.f};
    float q2r[2] = {0.f, 0.f};

    // row pointers for h: row = wrow + 8*h + g, col offset 2t
    const float* rp[2];
    #pragma unroll
    for (int h = 0; h < 2; ++h)
        rp[h] = emb + (rowbase + wrow + 8 * h + g) * 768 + 2 * t;

    // raw A double buffer (registers), preload chunk 0
    float2 raw[2][2][2];     // [buf][h][v0/v1]
    #pragma unroll
    for (int h = 0; h < 2; ++h) {
        raw[0][h][0] = __ldg((const float2*)(rp[h]));
        raw[0][h][1] = __ldg((const float2*)(rp[h] + 8));
    }

    #pragma unroll 2
    for (int ch = 0; ch < NCH; ++ch) {
        const int pb = ch & 1;

        // ---- convert raw A -> fp16 fragments + stats ----
        uint32_t ah[4];
        #pragma unroll
        for (int h = 0; h < 2; ++h) {
            const float2 v0 = raw[pb][h][0];
            const float2 v1 = raw[pb][h][1];
            ah[h]     = pack_f16x2(v0.y, v0.x);
            ah[h + 2] = pack_f16x2(v1.y, v1.x);
            s2r[h] += (v0.x + v0.y) + (v1.x + v1.y);
            q2r[h] = fmaf(v0.x, v0.x, q2r[h]);
            q2r[h] = fmaf(v0.y, v0.y, q2r[h]);
            q2r[h] = fmaf(v1.x, v1.x, q2r[h]);
            q2r[h] = fmaf(v1.y, v1.y, q2r[h]);
        }

        // ---- prefetch A raw for ch+1 (latency hidden behind MMA phase) ----
        if (ch + 1 < NCH) {
            const float* base0 = rp[0] + (ch + 1) * 16;
            const float* base1 = rp[1] + (ch + 1) * 16;
            raw[pb ^ 1][0][0] = __ldg((const float2*)(base0));
            raw[pb ^ 1][0][1] = __ldg((const float2*)(base0 + 8));
            raw[pb ^ 1][1][0] = __ldg((const float2*)(base1));
            raw[pb ^ 1][1][1] = __ldg((const float2*)(base1 + 8));
        }

        // ---- prefetch next B chunk, wait for current ----
        if (ch + 1 < NCH) {
            if (tid < 192) {
                const int buf = (ch + 1) & 1;
                cpa16(smem_u32(&sB[buf][tid * 16]),
                      (const char*)g_Bhi16 + (ch + 1) * 3072 + tid * 16);
                cpa16(smem_u32(&sB[buf][3072 + tid * 16]),
                      (const char*)g_Blo16 + (ch + 1) * 3072 + tid * 16);
            }
            asm volatile("cp.async.commit_group;" ::: "memory");
            asm volatile("cp.async.wait_group 1;" ::: "memory");
        } else {
            asm volatile("cp.async.wait_group 0;" ::: "memory");
        }
        __syncthreads();

        // ---- MMAs: 2 passes (B hi, B lo); same-acc deps 12 MMAs apart ----
        const unsigned char* base = sB[pb];
        #pragma unroll
        for (int j = 0; j < 12; ++j) {
            const uint2 bh = *(const uint2*)(base + j * 256 + l * 8);
            mma16816(acc[j], ah, bh);
        }
        #pragma unroll
        for (int j = 0; j < 12; ++j) {
            const uint2 bl = *(const uint2*)(base + 3072 + j * 256 + l * 8);
            mma16816(acc[j], ah, bl);
        }
        __syncthreads();   // everyone done reading before this buf is refilled
    }

    // ---- row stats: reduce over the 4 quad lanes, add tree tail ----
    #pragma unroll
    for (int m = 1; m <= 2; m <<= 1) {
        #pragma unroll
        for (int h = 0; h < 2; ++h) {
            s2r[h] += __shfl_xor_sync(0xffffffffu, s2r[h], m);
            q2r[h] += __shfl_xor_sync(0xffffffffu, q2r[h], m);
        }
    }
    if (t == 0) {
        #pragma unroll
        for (int h = 0; h < 2; ++h) {
            const int lr = wrow + 8 * h + g;
            const size_t gr = rowbase + lr;
            const float t0 = __ldg(&tree[gr * 3 + 0]);
            const float t1 = __ldg(&tree[gr * 3 + 1]);
            const float t2 = __ldg(&tree[gr * 3 + 2]);
            const float s = s2r[h] + t0 + t1 + t2;
            const float q = q2r[h] + t0 * t0 + t1 * t1 + t2 * t2;
            const float mu = s * (1.0f / 771.0f);
            const float rs = rsqrtf(q * (1.0f / 771.0f) - mu * mu + 1e-5f);
            sMU[lr] = mu; sRS[lr] = rs;
            sT[lr * 3 + 0] = t0; sT[lr * 3 + 1] = t1; sT[lr * 3 + 2] = t2;
        }
    }
    __syncthreads();

    // ---- epilogue: LN-fold + bias + exact GELU + GEMM2 partials ----
    float mu[2], rs[2], tv[2][3];
    #pragma unroll
    for (int h = 0; h < 2; ++h) {
        const int lr = wrow + 8 * h + g;
        mu[h] = sMU[lr]; rs[h] = sRS[lr];
        tv[h][0] = sT[lr * 3 + 0];
        tv[h][1] = sT[lr * 3 + 1];
        tv[h][2] = sT[lr * 3 + 2];
    }
    float o[2][3];
    #pragma unroll
    for (int h = 0; h < 2; ++h)
        #pragma unroll
        for (int c = 0; c < 3; ++c) o[h][c] = 0.f;

    #pragma unroll
    for (int j = 0; j < 12; ++j) {
        const int n0 = 8 * j + 2 * t;
        float c2v[2] = {sC2[n0], sC2[n0 + 1]};
        float c1v[2] = {sC1[n0], sC1[n0 + 1]};
        float wt0[2] = {sWT[n0], sWT[n0 + 1]};
        float wt1[2] = {sWT[HD + n0], sWT[HD + n0 + 1]};
        float wt2[2] = {sWT[2 * HD + n0], sWT[2 * HD + n0 + 1]};
        float w2v[2][3];
        #pragma unroll
        for (int cc = 0; cc < 2; ++cc)
            #pragma unroll
            for (int c = 0; c < 3; ++c)
                w2v[cc][c] = sW2[(n0 + cc) * 3 + c];

        #pragma unroll
        for (int h = 0; h < 2; ++h) {
            #pragma unroll
            for (int cc = 0; cc < 2; ++cc) {
                const float a = acc[j][2 * h + cc];
                const float tail = tv[h][0] * wt0[cc] +
                                   tv[h][1] * wt1[cc] +
                                   tv[h][2] * wt2[cc];
                const float y = rs[h] * (a + tail - mu[h] * c2v[cc]) + c1v[cc];
                const float gl = 0.5f * y * (1.0f + erff(y * 0.70710678118654752f));
                o[h][0] = fmaf(gl, w2v[cc][0], o[h][0]);
                o[h][1] = fmaf(gl, w2v[cc][1], o[h][1]);
                o[h][2] = fmaf(gl, w2v[cc][2], o[h][2]);
            }
        }
    }

    #pragma unroll
    for (int m = 1; m <= 2; m <<= 1)
        #pragma unroll
        for (int h = 0; h < 2; ++h)
            #pragma unroll
            for (int c = 0; c < 3; ++c)
                o[h][c] += __shfl_xor_sync(0xffffffffu, o[h][c], m);

    if (t == 0) {
        const float b20 = __ldg(&b2[0]);
        const float b21 = __ldg(&b2[1]);
        const float b22 = __ldg(&b2[2]);
        #pragma unroll
        for (int h = 0; h < 2; ++h) {
            const size_t gr = rowbase + wrow + 8 * h + g;
            out[gr * 3 + 0] = o[h][0] + b20;
            out[gr * 3 + 1] = o[h][1] + b21;
            out[gr * 3 + 2] = o[h][2] + b22;
        }
    }
}

extern "C" void kernel_launch(void* const* d_in, const int* in_sizes, int n_in,
                              void* d_out, int out_size) {
    const float* emb   = (const float*)d_in[0];
    const float* tree  = (const float*)d_in[1];
    const float* gamma = (const float*)d_in[2];
    const float* beta  = (const float*)d_in[3];
    const float* w1    = (const float*)d_in[4];
    const float* b1    = (const float*)d_in[5];
    const float* w2    = (const float*)d_in[6];
    const float* b2    = (const float*)d_in[7];
    float* out = (float*)d_out;

    const int B = in_sizes[0] / 768;

    fh_prep_b<<<(768 * HD + 255) / 256, 256>>>(gamma, w1);
    fh_prep_c<<<HD, 256>>>(gamma, beta, w1, b1);
    fh_main<<<B / TB, THREADS>>>(emb, tree, w2, b2, out);
}